// round 1
// baseline (speedup 1.0000x reference)
#include <cuda_runtime.h>
#include <math.h>

// 1/sqrt(1 + 1e-3)
#define ISRC 0.9995003746877732f
#define XS 65   // padded row stride of x in smem (bank-conflict-free column reads)

// scratch (static __device__ arrays: allocation-free)
__device__ float g_x[64 * 32768];        // GNN output, (B, N*64) row-major
__device__ float g_part[128 * 64 * 128]; // split-K partials: (kchunk, b, d)

// ----------------------------------------------------------------------------
// GNN layer: pairwise S/T + fused GEMM + bias/mask/BN/tanh, all in smem.
//   y[i,o] = sum_k x[i,k]*A[k,o]  +  (m_i*S_i - 1) * sum_k x[i,k]*A[F+k,o]
//            + (m_i*T_i)*A[2F,o] + b[o],   then *m_i, BN, tanh
// ----------------------------------------------------------------------------
template <int F, int ND>
__device__ __forceinline__ void do_layer(
    float* x_s, float* A_s, float* c_s, float* s_s, float* t_s, float* m_s,
    float* cn_s,
    const float* __restrict__ A, const float* __restrict__ bias,
    const float* __restrict__ bng, const float* __restrict__ bnb)
{
    const int tid = threadIdx.x;
    constexpr int KT = 2 * F + 1;

    __syncthreads();  // previous layer fully done (x_s final, A_s/cn_s reads done)

    // stage layer weights + per-column constants
    for (int idx = tid; idx < KT * 64; idx += 512) A_s[idx] = A[idx];
    if (tid < 64) {
        cn_s[tid]        = bias[tid];
        cn_s[64 + tid]   = bng[tid] * ISRC;
        cn_s[128 + tid]  = bnb[tid];
    }
    // c = last ND features of own row (pad to 4 with zeros)
    {
        const float* xr = x_s + tid * XS;
        float4 cv;
        cv.x = xr[F - ND + 0];
        cv.y = xr[F - ND + 1];
        cv.z = (ND == 4) ? xr[F - 2] : 0.f;
        cv.w = (ND == 4) ? xr[F - 1] : 0.f;
        reinterpret_cast<float4*>(c_s)[tid] = cv;
    }
    __syncthreads();

    // pairwise sums: thread i loops all j (broadcast LDS.128)
    {
        const float4 ci = reinterpret_cast<const float4*>(c_s)[tid];
        float S = 0.f, T = 0.f;
#pragma unroll 8
        for (int j = 0; j < 512; j++) {
            float4 cj = reinterpret_cast<const float4*>(c_s)[j];
            float dx = cj.x - ci.x;
            float dy = cj.y - ci.y;
            float d = dx * dx + dy * dy;
            if (ND == 4) {
                float dz = cj.z - ci.z;
                float dw = cj.w - ci.w;
                d += dz * dz + dw * dw;
            }
            float w = __expf(-10.f * d);
            S += w;
            T = fmaf(d, w, T);
        }
        float m = m_s[tid];
        s_s[tid] = fmaf(m, S, -1.f);  // (m*S - 1)
        t_s[tid] = m * T;
    }
    __syncthreads();

    // GEMM: 512 threads, 2 row-halves of 256; each thread 4 rows x 8 cols,
    // dual accumulators (u for A_top, v for A_mid; v scaled by s_i at the end).
    const int cs0   = (tid & 7) * 8;
    const int rslot = tid >> 3;  // 0..63
#pragma unroll 1
    for (int half = 0; half < 2; half++) {
        const int r0 = half * 256 + rslot * 4;
        float u[4][8], v[4][8];
#pragma unroll
        for (int r = 0; r < 4; r++)
#pragma unroll
            for (int c = 0; c < 8; c++) { u[r][c] = 0.f; v[r][c] = 0.f; }

        const float* xp0 = x_s + (r0 + 0) * XS;
        const float* xp1 = x_s + (r0 + 1) * XS;
        const float* xp2 = x_s + (r0 + 2) * XS;
        const float* xp3 = x_s + (r0 + 3) * XS;
#pragma unroll 4
        for (int k = 0; k < F; k++) {
            float4 a0 = *reinterpret_cast<const float4*>(&A_s[k * 64 + cs0]);
            float4 a1 = *reinterpret_cast<const float4*>(&A_s[k * 64 + cs0 + 4]);
            float4 q0 = *reinterpret_cast<const float4*>(&A_s[(F + k) * 64 + cs0]);
            float4 q1 = *reinterpret_cast<const float4*>(&A_s[(F + k) * 64 + cs0 + 4]);
            float xv[4];
            xv[0] = xp0[k]; xv[1] = xp1[k]; xv[2] = xp2[k]; xv[3] = xp3[k];
#pragma unroll
            for (int r = 0; r < 4; r++) {
                u[r][0] = fmaf(xv[r], a0.x, u[r][0]);
                u[r][1] = fmaf(xv[r], a0.y, u[r][1]);
                u[r][2] = fmaf(xv[r], a0.z, u[r][2]);
                u[r][3] = fmaf(xv[r], a0.w, u[r][3]);
                u[r][4] = fmaf(xv[r], a1.x, u[r][4]);
                u[r][5] = fmaf(xv[r], a1.y, u[r][5]);
                u[r][6] = fmaf(xv[r], a1.z, u[r][6]);
                u[r][7] = fmaf(xv[r], a1.w, u[r][7]);
                v[r][0] = fmaf(xv[r], q0.x, v[r][0]);
                v[r][1] = fmaf(xv[r], q0.y, v[r][1]);
                v[r][2] = fmaf(xv[r], q0.z, v[r][2]);
                v[r][3] = fmaf(xv[r], q0.w, v[r][3]);
                v[r][4] = fmaf(xv[r], q1.x, v[r][4]);
                v[r][5] = fmaf(xv[r], q1.y, v[r][5]);
                v[r][6] = fmaf(xv[r], q1.z, v[r][6]);
                v[r][7] = fmaf(xv[r], q1.w, v[r][7]);
            }
        }
        __syncthreads();  // all reads of this half's rows done before overwrite
#pragma unroll
        for (int r = 0; r < 4; r++) {
            const int i = r0 + r;
            const float s = s_s[i], t = t_s[i], m = m_s[i];
#pragma unroll
            for (int c = 0; c < 8; c++) {
                float y = fmaf(s, v[r][c], u[r][c]);
                y = fmaf(t, A_s[2 * F * 64 + cs0 + c], y);
                y += cn_s[cs0 + c];
                y *= m;
                x_s[i * XS + cs0 + c] =
                    tanhf(fmaf(cn_s[64 + cs0 + c], y, cn_s[128 + cs0 + c]));
            }
        }
        // next half reads disjoint rows -> no barrier needed here
    }
}

// ----------------------------------------------------------------------------
__global__ __launch_bounds__(512, 1) void gnn_kernel(
    const float* __restrict__ xx,
    const float* __restrict__ e1, const float* __restrict__ e2,
    const float* __restrict__ e3,
    const float* __restrict__ A0, const float* __restrict__ b0,
    const float* __restrict__ Ar, const float* __restrict__ br,
    const float* __restrict__ bng, const float* __restrict__ bnb)
{
    extern __shared__ float sm[];
    float* x_s  = sm;                  // 512*65
    float* A_s  = x_s + 512 * XS;      // 129*64
    float* c_s  = A_s + 129 * 64;      // 512*4
    float* s_s  = c_s + 512 * 4;       // 512
    float* t_s  = s_s + 512;           // 512
    float* m_s  = t_s + 512;           // 512
    float* cn_s = m_s + 512;           // 192

    const int b   = blockIdx.x;
    const int tid = threadIdx.x;

    // build initial 33 features for own row
    {
        const float* row = xx + ((size_t)b * 512 + tid) * 30;
        float m = row[0];
        m_s[tid] = m;
        int i1 = (int)fabsf(row[27]);
        int i2 = (int)fabsf(row[28]);
        int i3 = (int)fabsf(row[29]);
        float* xr = x_s + tid * XS;
        xr[0] = e1[2 * i1];     xr[1] = e1[2 * i1 + 1];
        xr[2] = e2[2 * i2];     xr[3] = e2[2 * i2 + 1];
        xr[4] = e3[2 * i3];     xr[5] = e3[2 * i3 + 1];
#pragma unroll
        for (int k = 0; k < 27; k++) xr[6 + k] = row[k];
    }

    do_layer<33, 2>(x_s, A_s, c_s, s_s, t_s, m_s, cn_s, A0, b0, bng, bnb);
#pragma unroll 1
    for (int l = 0; l < 4; l++) {
        do_layer<64, 4>(x_s, A_s, c_s, s_s, t_s, m_s, cn_s,
                        Ar + l * 129 * 64, br + l * 64,
                        bng + (l + 1) * 64, bnb + (l + 1) * 64);
    }
    __syncthreads();
    float* out = g_x + (size_t)b * 32768;
    for (int idx = tid; idx < 32768; idx += 512)
        out[idx] = x_s[(idx >> 6) * XS + (idx & 63)];
}

// ----------------------------------------------------------------------------
// Dense layer 0 split-K: 128 CTAs, each owns a K-chunk of 256.
// Deterministic: partials stored, reduced in finalize (no float atomics).
// ----------------------------------------------------------------------------
__global__ __launch_bounds__(256, 1) void dense0_kernel(const float* __restrict__ W)
{
    extern __shared__ float sm[];
    float* Xs = sm;              // 64 x 256
    float* Ws = Xs + 64 * 256;   // 256 x 128
    const int tid = threadIdx.x;
    const int kc  = blockIdx.x;

    for (int idx = tid; idx < 64 * 256; idx += 256) {
        int b = idx >> 8, k = idx & 255;
        Xs[idx] = g_x[(size_t)b * 32768 + kc * 256 + k];
    }
    const float* wsrc = W + (size_t)kc * 256 * 128;
    for (int idx = tid; idx < 256 * 128; idx += 256) Ws[idx] = wsrc[idx];
    __syncthreads();

    const int bs = tid >> 5;   // 0..7  -> rows b = bs*8..bs*8+7
    const int ds = tid & 31;   // 0..31 -> cols d = ds*4..ds*4+3
    float acc[8][4];
#pragma unroll
    for (int r = 0; r < 8; r++)
#pragma unroll
        for (int j = 0; j < 4; j++) acc[r][j] = 0.f;

#pragma unroll 4
    for (int k = 0; k < 256; k++) {
        float4 w4 = *reinterpret_cast<const float4*>(&Ws[k * 128 + ds * 4]);
#pragma unroll
        for (int r = 0; r < 8; r++) {
            float xv = Xs[(bs * 8 + r) * 256 + k];  // warp-broadcast
            acc[r][0] = fmaf(xv, w4.x, acc[r][0]);
            acc[r][1] = fmaf(xv, w4.y, acc[r][1]);
            acc[r][2] = fmaf(xv, w4.z, acc[r][2]);
            acc[r][3] = fmaf(xv, w4.w, acc[r][3]);
        }
    }
    float* dst = g_part + (size_t)kc * 8192;
#pragma unroll
    for (int r = 0; r < 8; r++)
#pragma unroll
        for (int j = 0; j < 4; j++)
            dst[(bs * 8 + r) * 128 + ds * 4 + j] = acc[r][j];
}

// ----------------------------------------------------------------------------
// Finalize: reduce partials, BN+sigmoid, dense1, BN+sigmoid, W2, write (64,4)
// ----------------------------------------------------------------------------
__global__ __launch_bounds__(128, 1) void finalize_kernel(
    const float* __restrict__ db0, const float* __restrict__ dW1,
    const float* __restrict__ db1, const float* __restrict__ dbng,
    const float* __restrict__ dbnb, const float* __restrict__ W2,
    const float* __restrict__ b2, float* __restrict__ out)
{
    __shared__ float h0[128];
    __shared__ float h1[128];
    const int b = blockIdx.x;
    const int d = threadIdx.x;

    float a = db0[d];
#pragma unroll 4
    for (int kc = 0; kc < 128; kc++) a += g_part[(size_t)kc * 8192 + b * 128 + d];
    a = fmaf(dbng[d] * ISRC, a, dbnb[d]);
    h0[d] = 1.f / (1.f + __expf(-a));
    __syncthreads();

    float s = 0.f;
#pragma unroll 8
    for (int k = 0; k < 128; k++) s = fmaf(h0[k], dW1[k * 128 + d], s);
    s += db1[d];
    s = fmaf(dbng[128 + d] * ISRC, s, dbnb[128 + d]);
    h1[d] = 1.f / (1.f + __expf(-s));
    __syncthreads();

    if (d < 4) {
        float o = 0.f;
        if (d < 2) {
            o = b2[d];
            for (int k = 0; k < 128; k++) o = fmaf(h1[k], W2[k * 2 + d], o);
        }
        out[b * 4 + d] = o;
    }
}

// ----------------------------------------------------------------------------
extern "C" void kernel_launch(void* const* d_in, const int* in_sizes, int n_in,
                              void* d_out, int out_size)
{
    const float* xx   = (const float*)d_in[0];
    const float* emb1 = (const float*)d_in[1];
    const float* emb2 = (const float*)d_in[2];
    const float* emb3 = (const float*)d_in[3];
    const float* A0   = (const float*)d_in[4];
    const float* b0   = (const float*)d_in[5];
    const float* Ar   = (const float*)d_in[6];
    const float* br   = (const float*)d_in[7];
    const float* bng  = (const float*)d_in[8];
    const float* bnb  = (const float*)d_in[9];
    const float* dW0  = (const float*)d_in[10];
    const float* db0  = (const float*)d_in[11];
    const float* dW1  = (const float*)d_in[12];
    const float* db1  = (const float*)d_in[13];
    const float* dbng = (const float*)d_in[14];
    const float* dbnb = (const float*)d_in[15];
    const float* W2   = (const float*)d_in[16];
    const float* b2   = (const float*)d_in[17];
    float* out = (float*)d_out;

    const int GNN_SMEM = (512 * XS + 129 * 64 + 512 * 4 + 512 * 3 + 192) * 4; // 181248
    const int D0_SMEM  = (64 * 256 + 256 * 128) * 4;                          // 196608

    cudaFuncSetAttribute(gnn_kernel, cudaFuncAttributeMaxDynamicSharedMemorySize,
                         GNN_SMEM);
    cudaFuncSetAttribute(dense0_kernel, cudaFuncAttributeMaxDynamicSharedMemorySize,
                         D0_SMEM);

    gnn_kernel<<<64, 512, GNN_SMEM>>>(xx, emb1, emb2, emb3, A0, b0, Ar, br, bng, bnb);
    dense0_kernel<<<128, 256, D0_SMEM>>>(dW0);
    finalize_kernel<<<64, 128>>>(db0, dW1, db1, dbng, dbnb, W2, b2, out);
}